// round 2
// baseline (speedup 1.0000x reference)
#include <cuda_runtime.h>
#include <math.h>

#define B_SZ 64
#define T_SZ 128
#define F_SZ 512
#define H_SZ 1024
#define P_SZ 1024
#define A_SZ 32
#define R_SZ (B_SZ * T_SZ)      /* 8192 rows */
#define G_SZ (4 * H_SZ)         /* 4096 gate cols */
#define KSPLIT 4

// ---------------- scratch (static device globals; no allocations) ----------
__device__ float g_pre[R_SZ * P_SZ];            // 32 MB: pre-LN activations / LN output
__device__ float g_zx[(size_t)R_SZ * G_SZ];     // 128 MB: input-gate preacts, time-major [T][B][4H]
__device__ float g_hseq0[R_SZ * H_SZ];          // 32 MB
__device__ float g_hseq1[R_SZ * H_SZ];          // 32 MB
__device__ float g_hp[R_SZ * P_SZ];             // 32 MB
__device__ float g_zpart[KSPLIT][B_SZ * G_SZ];  // 4 MB: split-K partials of h@Wh
__device__ float g_c[B_SZ * H_SZ];
__device__ float g_h[B_SZ * H_SZ];

// ---------------- generic big GEMM: C = act(A[M,K] @ W[K,N] + bias) --------
// tile 128x64, BK=16, 256 threads, 8x4 per thread.
// ACT: 0 none, 1 relu.  PERM: 0 row-major C, 1 time-major scatter [T][B][N].
template <int ACT, int PERM>
__global__ __launch_bounds__(256) void gemm_main(
    const float* __restrict__ A, const float* __restrict__ W,
    const float* __restrict__ bias, float* __restrict__ C,
    int M, int N, int K)
{
    __shared__ float As[16][132];   // [k][m], padded
    __shared__ float Bs[16][64];

    const int tid = threadIdx.x;
    const int bm = blockIdx.y * 128;
    const int bn = blockIdx.x * 64;
    const int tx = tid & 15;        // N dir: 16 * 4
    const int ty = tid >> 4;        // M dir: 16 * 8

    float acc[8][4];
#pragma unroll
    for (int i = 0; i < 8; i++)
#pragma unroll
        for (int j = 0; j < 4; j++) acc[i][j] = 0.f;

    for (int k0 = 0; k0 < K; k0 += 16) {
        // A tile: 128x16 = 512 float4, 2 per thread, transpose into As[k][m]
#pragma unroll
        for (int t = 0; t < 2; t++) {
            int idx = tid + t * 256;
            int row = idx >> 2;
            int kq = (idx & 3) * 4;
            float4 v = *(const float4*)&A[(size_t)(bm + row) * K + k0 + kq];
            As[kq + 0][row] = v.x; As[kq + 1][row] = v.y;
            As[kq + 2][row] = v.z; As[kq + 3][row] = v.w;
        }
        // B tile: 16x64 = 256 float4, 1 per thread (N-guarded; N always mult of 4)
        {
            int row = tid >> 4;
            int c4 = (tid & 15) * 4;
            int col = bn + c4;
            float4 v = make_float4(0.f, 0.f, 0.f, 0.f);
            if (col < N) v = *(const float4*)&W[(size_t)(k0 + row) * N + col];
            *(float4*)&Bs[row][c4] = v;
        }
        __syncthreads();
#pragma unroll
        for (int k = 0; k < 16; k++) {
            float a[8], b[4];
            *(float4*)&a[0] = *(const float4*)&As[k][ty * 8];
            *(float4*)&a[4] = *(const float4*)&As[k][ty * 8 + 4];
            *(float4*)&b[0] = *(const float4*)&Bs[k][tx * 4];
#pragma unroll
            for (int i = 0; i < 8; i++)
#pragma unroll
                for (int j = 0; j < 4; j++) acc[i][j] = fmaf(a[i], b[j], acc[i][j]);
        }
        __syncthreads();
    }

    const int colb = bn + tx * 4;
    if (colb < N) {
        float4 bv = *(const float4*)&bias[colb];
#pragma unroll
        for (int i = 0; i < 8; i++) {
            int row = bm + ty * 8 + i;
            float4 o;
            o.x = acc[i][0] + bv.x; o.y = acc[i][1] + bv.y;
            o.z = acc[i][2] + bv.z; o.w = acc[i][3] + bv.w;
            if (ACT == 1) {
                o.x = fmaxf(o.x, 0.f); o.y = fmaxf(o.y, 0.f);
                o.z = fmaxf(o.z, 0.f); o.w = fmaxf(o.w, 0.f);
            }
            size_t off;
            if (PERM == 1) {
                int b = row / T_SZ, t = row % T_SZ;
                off = ((size_t)t * B_SZ + b) * N + colb;
            } else {
                off = (size_t)row * N + colb;
            }
            *(float4*)&C[off] = o;
        }
    }
}

// ---------------- LayerNorm + ReLU over rows of 1024 -----------------------
__global__ __launch_bounds__(256) void ln_relu_kernel(
    float* __restrict__ buf, const float* __restrict__ gamma,
    const float* __restrict__ beta)
{
    __shared__ float rs[8], rs2[8];
    const int row = blockIdx.x;
    float* p = buf + (size_t)row * P_SZ;
    const int tid = threadIdx.x;

    float4 v = *(const float4*)&p[tid * 4];
    float s = v.x + v.y + v.z + v.w;
    float s2 = v.x * v.x + v.y * v.y + v.z * v.z + v.w * v.w;
#pragma unroll
    for (int off = 16; off > 0; off >>= 1) {
        s += __shfl_xor_sync(0xFFFFFFFFu, s, off);
        s2 += __shfl_xor_sync(0xFFFFFFFFu, s2, off);
    }
    if ((tid & 31) == 0) { rs[tid >> 5] = s; rs2[tid >> 5] = s2; }
    __syncthreads();
    float tot = 0.f, tot2 = 0.f;
#pragma unroll
    for (int i = 0; i < 8; i++) { tot += rs[i]; tot2 += rs2[i]; }
    const float mu = tot * (1.f / 1024.f);
    float var = tot2 * (1.f / 1024.f) - mu * mu;
    const float r = rsqrtf(var + 1e-6f);

    float4 g = *(const float4*)&gamma[tid * 4];
    float4 b = *(const float4*)&beta[tid * 4];
    float4 o;
    o.x = fmaxf((v.x - mu) * r * g.x + b.x, 0.f);
    o.y = fmaxf((v.y - mu) * r * g.y + b.y, 0.f);
    o.z = fmaxf((v.z - mu) * r * g.z + b.z, 0.f);
    o.w = fmaxf((v.w - mu) * r * g.w + b.w, 0.f);
    *(float4*)&p[tid * 4] = o;
}

// ---------------- recurrent GEMM: zpart[ks] = g_h[64,1024-chunk] @ Wh ------
// tile 64x128, BK=16, split-K = 4, 256 threads, 8x4 per thread.
__global__ __launch_bounds__(256) void lstm_gemm(const float* __restrict__ Wh)
{
    __shared__ float As[16][68];
    __shared__ float Bs[16][128];

    const int tid = threadIdx.x;
    const int bn = blockIdx.x * 128;
    const int ks = blockIdx.y;
    const int k_begin = ks * (H_SZ / KSPLIT);
    const int tx = tid & 31;        // N dir: 32 * 4
    const int ty = tid >> 5;        // M dir: 8 * 8

    float acc[8][4];
#pragma unroll
    for (int i = 0; i < 8; i++)
#pragma unroll
        for (int j = 0; j < 4; j++) acc[i][j] = 0.f;

    for (int k0 = k_begin; k0 < k_begin + H_SZ / KSPLIT; k0 += 16) {
        {   // A tile 64x16 = 256 float4, 1 per thread
            int row = tid >> 2;
            int kq = (tid & 3) * 4;
            float4 v = *(const float4*)&g_h[row * H_SZ + k0 + kq];
            As[kq + 0][row] = v.x; As[kq + 1][row] = v.y;
            As[kq + 2][row] = v.z; As[kq + 3][row] = v.w;
        }
#pragma unroll
        for (int t = 0; t < 2; t++) {   // B tile 16x128 = 512 float4
            int idx = tid + t * 256;
            int row = idx >> 5;
            int c4 = (idx & 31) * 4;
            *(float4*)&Bs[row][c4] =
                *(const float4*)&Wh[(size_t)(k0 + row) * G_SZ + bn + c4];
        }
        __syncthreads();
#pragma unroll
        for (int k = 0; k < 16; k++) {
            float a[8], b[4];
            *(float4*)&a[0] = *(const float4*)&As[k][ty * 8];
            *(float4*)&a[4] = *(const float4*)&As[k][ty * 8 + 4];
            *(float4*)&b[0] = *(const float4*)&Bs[k][tx * 4];
#pragma unroll
            for (int i = 0; i < 8; i++)
#pragma unroll
                for (int j = 0; j < 4; j++) acc[i][j] = fmaf(a[i], b[j], acc[i][j]);
        }
        __syncthreads();
    }

    float* zp = g_zpart[ks];
#pragma unroll
    for (int i = 0; i < 8; i++) {
        int row = ty * 8 + i;
        float4 o = make_float4(acc[i][0], acc[i][1], acc[i][2], acc[i][3]);
        *(float4*)&zp[(size_t)row * G_SZ + bn + tx * 4] = o;
    }
}

// ---------------- gate pointwise: c,h update + sequence scatter ------------
__device__ __forceinline__ float sigmoidf_(float x) { return 1.f / (1.f + expf(-x)); }

__global__ __launch_bounds__(256) void lstm_gates(
    const float* __restrict__ zx_t, float* __restrict__ hseq, int t)
{
    const int idx = blockIdx.x * 256 + threadIdx.x;   // 0..65535
    const int b = idx >> 10;
    const int u = idx & 1023;
    const size_t base = (size_t)b * G_SZ;

    float zi = zx_t[base + u];
    float zf = zx_t[base + H_SZ + u];
    float zg = zx_t[base + 2 * H_SZ + u];
    float zo = zx_t[base + 3 * H_SZ + u];
#pragma unroll
    for (int s = 0; s < KSPLIT; s++) {
        zi += g_zpart[s][base + u];
        zf += g_zpart[s][base + H_SZ + u];
        zg += g_zpart[s][base + 2 * H_SZ + u];
        zo += g_zpart[s][base + 3 * H_SZ + u];
    }
    const float ig = sigmoidf_(zi);
    const float fg = sigmoidf_(zf);
    const float gg = tanhf(zg);
    const float og = sigmoidf_(zo);
    const float c_new = fg * g_c[idx] + ig * gg;
    const float h_new = og * tanhf(c_new);
    g_c[idx] = c_new;
    g_h[idx] = h_new;
    hseq[((size_t)b * T_SZ + t) * H_SZ + u] = h_new;
}

// ---------------- state init / export --------------------------------------
__global__ __launch_bounds__(256) void copy_state(
    const float* __restrict__ c0, const float* __restrict__ h0)
{
    int i = blockIdx.x * 256 + threadIdx.x;
    g_c[i] = c0[i];
    g_h[i] = h0[i];
}

__global__ __launch_bounds__(256) void copy_out(
    float* __restrict__ dst_c, float* __restrict__ dst_h)
{
    int i = blockIdx.x * 256 + threadIdx.x;
    dst_c[i] = g_c[i];
    dst_h[i] = g_h[i];
}

// ---------------- launch ----------------------------------------------------
extern "C" void kernel_launch(void* const* d_in, const int* in_sizes, int n_in,
                              void* d_out, int out_size)
{
    const float* x        = (const float*)d_in[0];
    const float* c0       = (const float*)d_in[1];
    const float* h0       = (const float*)d_in[2];
    const float* W_pre    = (const float*)d_in[3];
    const float* b_pre    = (const float*)d_in[4];
    const float* ln_scale = (const float*)d_in[5];
    const float* ln_bias  = (const float*)d_in[6];
    const float* Wi0      = (const float*)d_in[7];
    const float* Wh0      = (const float*)d_in[8];
    const float* b0       = (const float*)d_in[9];
    const float* Wi1      = (const float*)d_in[10];
    const float* Wh1      = (const float*)d_in[11];
    const float* b1       = (const float*)d_in[12];
    const float* W_post   = (const float*)d_in[13];
    const float* b_post   = (const float*)d_in[14];
    const float* W_out    = (const float*)d_in[15];
    const float* b_out    = (const float*)d_in[16];
    float* out = (float*)d_out;

    float* g_pre_p;   cudaGetSymbolAddress((void**)&g_pre_p, g_pre);
    float* g_zx_p;    cudaGetSymbolAddress((void**)&g_zx_p, g_zx);
    float* g_hseq0_p; cudaGetSymbolAddress((void**)&g_hseq0_p, g_hseq0);
    float* g_hseq1_p; cudaGetSymbolAddress((void**)&g_hseq1_p, g_hseq1);
    float* g_hp_p;    cudaGetSymbolAddress((void**)&g_hp_p, g_hp);

    // 1) pre dense: [8192,512]@[512,1024]
    gemm_main<0, 0><<<dim3(P_SZ / 64, R_SZ / 128), 256>>>(
        x, W_pre, b_pre, g_pre_p, R_SZ, P_SZ, F_SZ);
    // 2) LayerNorm + ReLU, in place
    ln_relu_kernel<<<R_SZ, 256>>>(g_pre_p, ln_scale, ln_bias);
    // 3) layer-0 input gates, time-major: [8192,1024]@[1024,4096]
    gemm_main<0, 1><<<dim3(G_SZ / 64, R_SZ / 128), 256>>>(
        g_pre_p, Wi0, b0, g_zx_p, R_SZ, G_SZ, P_SZ);

    // 4) layer-0 recurrence
    copy_state<<<256, 256>>>(c0, h0);
    for (int t = 0; t < T_SZ; t++) {
        lstm_gemm<<<dim3(G_SZ / 128, KSPLIT), 256>>>(Wh0);
        lstm_gates<<<256, 256>>>(g_zx_p + (size_t)t * B_SZ * G_SZ, g_hseq0_p, t);
    }
    copy_out<<<256, 256>>>(out, out + 2 * B_SZ * H_SZ);   // c1, h1

    // 5) layer-1 input gates (reuse g_zx)
    gemm_main<0, 1><<<dim3(G_SZ / 64, R_SZ / 128), 256>>>(
        g_hseq0_p, Wi1, b1, g_zx_p, R_SZ, G_SZ, H_SZ);

    // 6) layer-1 recurrence
    copy_state<<<256, 256>>>(c0 + B_SZ * H_SZ, h0 + B_SZ * H_SZ);
    for (int t = 0; t < T_SZ; t++) {
        lstm_gemm<<<dim3(G_SZ / 128, KSPLIT), 256>>>(Wh1);
        lstm_gates<<<256, 256>>>(g_zx_p + (size_t)t * B_SZ * G_SZ, g_hseq1_p, t);
    }
    copy_out<<<256, 256>>>(out + B_SZ * H_SZ, out + 3 * B_SZ * H_SZ);  // c2, h2

    // 7) post dense + relu: [8192,1024]@[1024,1024]
    gemm_main<1, 0><<<dim3(P_SZ / 64, R_SZ / 128), 256>>>(
        g_hseq1_p, W_post, b_post, g_hp_p, R_SZ, P_SZ, H_SZ);
    // 8) logits: [8192,1024]@[1024,32] -> out[262144:]
    gemm_main<0, 0><<<dim3(1, R_SZ / 128), 256>>>(
        g_hp_p, W_out, b_out, out + 4 * B_SZ * H_SZ, R_SZ, A_SZ, P_SZ);
}

// round 3
// speedup vs baseline: 1.0452x; 1.0452x over previous
#include <cuda_runtime.h>
#include <math.h>

#define B_SZ 64
#define T_SZ 128
#define F_SZ 512
#define H_SZ 1024
#define P_SZ 1024
#define A_SZ 32
#define R_SZ (B_SZ * T_SZ)      /* 8192 rows */
#define G_SZ (4 * H_SZ)         /* 4096 gate cols */
#define KSPLIT 4

// ---------------- scratch (static device globals; no allocations) ----------
__device__ float g_pre[R_SZ * P_SZ];            // 32 MB: pre-LN activations / LN output
__device__ float g_zx[(size_t)R_SZ * G_SZ];     // 128 MB: input-gate preacts, time-major [T][B][4H]
__device__ float g_hseq0[R_SZ * H_SZ];          // 32 MB
__device__ float g_hseq1[R_SZ * H_SZ];          // 32 MB
__device__ float g_hp[R_SZ * P_SZ];             // 32 MB
__device__ float g_zpart[KSPLIT][B_SZ * G_SZ];  // 4 MB: split-K partials of h@Wh
__device__ float g_c[B_SZ * H_SZ];
__device__ float g_h[B_SZ * H_SZ];

// ---------------- generic big GEMM: C = act(A[M,K] @ W[K,N] + bias) --------
// tile 128x64, BK=16, 256 threads, 8x4 per thread.
// ACT: 0 none, 1 relu.  PERM: 0 row-major C, 1 time-major scatter [T][B][N].
template <int ACT, int PERM>
__global__ __launch_bounds__(256) void gemm_main(
    const float* __restrict__ A, const float* __restrict__ W,
    const float* __restrict__ bias, float* __restrict__ C,
    int M, int N, int K)
{
    __shared__ float As[16][132];   // [k][m], padded
    __shared__ float Bs[16][64];

    const int tid = threadIdx.x;
    const int bm = blockIdx.y * 128;
    const int bn = blockIdx.x * 64;
    const int tx = tid & 15;        // N dir: 16 * 4
    const int ty = tid >> 4;        // M dir: 16 * 8

    float acc[8][4];
#pragma unroll
    for (int i = 0; i < 8; i++)
#pragma unroll
        for (int j = 0; j < 4; j++) acc[i][j] = 0.f;

    for (int k0 = 0; k0 < K; k0 += 16) {
        // A tile: 128x16 = 512 float4, 2 per thread, transpose into As[k][m]
#pragma unroll
        for (int t = 0; t < 2; t++) {
            int idx = tid + t * 256;
            int row = idx >> 2;
            int kq = (idx & 3) * 4;
            float4 v = *(const float4*)&A[(size_t)(bm + row) * K + k0 + kq];
            As[kq + 0][row] = v.x; As[kq + 1][row] = v.y;
            As[kq + 2][row] = v.z; As[kq + 3][row] = v.w;
        }
        // B tile: 16x64 = 256 float4, 1 per thread (N-guarded; N always mult of 4)
        {
            int row = tid >> 4;
            int c4 = (tid & 15) * 4;
            int col = bn + c4;
            float4 v = make_float4(0.f, 0.f, 0.f, 0.f);
            if (col < N) v = *(const float4*)&W[(size_t)(k0 + row) * N + col];
            *(float4*)&Bs[row][c4] = v;
        }
        __syncthreads();
#pragma unroll
        for (int k = 0; k < 16; k++) {
            float a[8], b[4];
            *(float4*)&a[0] = *(const float4*)&As[k][ty * 8];
            *(float4*)&a[4] = *(const float4*)&As[k][ty * 8 + 4];
            *(float4*)&b[0] = *(const float4*)&Bs[k][tx * 4];
#pragma unroll
            for (int i = 0; i < 8; i++)
#pragma unroll
                for (int j = 0; j < 4; j++) acc[i][j] = fmaf(a[i], b[j], acc[i][j]);
        }
        __syncthreads();
    }

    const int colb = bn + tx * 4;
    if (colb < N) {
        float4 bv = *(const float4*)&bias[colb];
#pragma unroll
        for (int i = 0; i < 8; i++) {
            int row = bm + ty * 8 + i;
            float4 o;
            o.x = acc[i][0] + bv.x; o.y = acc[i][1] + bv.y;
            o.z = acc[i][2] + bv.z; o.w = acc[i][3] + bv.w;
            if (ACT == 1) {
                o.x = fmaxf(o.x, 0.f); o.y = fmaxf(o.y, 0.f);
                o.z = fmaxf(o.z, 0.f); o.w = fmaxf(o.w, 0.f);
            }
            size_t off;
            if (PERM == 1) {
                int b = row / T_SZ, t = row % T_SZ;
                off = ((size_t)t * B_SZ + b) * N + colb;
            } else {
                off = (size_t)row * N + colb;
            }
            *(float4*)&C[off] = o;
        }
    }
}

// ---------------- LayerNorm + ReLU over rows of 1024 -----------------------
__global__ __launch_bounds__(256) void ln_relu_kernel(
    float* __restrict__ buf, const float* __restrict__ gamma,
    const float* __restrict__ beta)
{
    __shared__ float rs[8], rs2[8];
    const int row = blockIdx.x;
    float* p = buf + (size_t)row * P_SZ;
    const int tid = threadIdx.x;

    float4 v = *(const float4*)&p[tid * 4];
    float s = v.x + v.y + v.z + v.w;
    float s2 = v.x * v.x + v.y * v.y + v.z * v.z + v.w * v.w;
#pragma unroll
    for (int off = 16; off > 0; off >>= 1) {
        s += __shfl_xor_sync(0xFFFFFFFFu, s, off);
        s2 += __shfl_xor_sync(0xFFFFFFFFu, s2, off);
    }
    if ((tid & 31) == 0) { rs[tid >> 5] = s; rs2[tid >> 5] = s2; }
    __syncthreads();
    float tot = 0.f, tot2 = 0.f;
#pragma unroll
    for (int i = 0; i < 8; i++) { tot += rs[i]; tot2 += rs2[i]; }
    const float mu = tot * (1.f / 1024.f);
    float var = tot2 * (1.f / 1024.f) - mu * mu;
    const float r = rsqrtf(var + 1e-6f);

    float4 g = *(const float4*)&gamma[tid * 4];
    float4 b = *(const float4*)&beta[tid * 4];
    float4 o;
    o.x = fmaxf((v.x - mu) * r * g.x + b.x, 0.f);
    o.y = fmaxf((v.y - mu) * r * g.y + b.y, 0.f);
    o.z = fmaxf((v.z - mu) * r * g.z + b.z, 0.f);
    o.w = fmaxf((v.w - mu) * r * g.w + b.w, 0.f);
    *(float4*)&p[tid * 4] = o;
}

// ---------------- recurrent GEMM: zpart[ks] = g_h[64,1024-chunk] @ Wh ------
// tile 64x128, BK=16, split-K = 4, 256 threads, 8x4 per thread.
__global__ __launch_bounds__(256) void lstm_gemm(const float* __restrict__ Wh)
{
    __shared__ float As[16][68];
    __shared__ float Bs[16][128];

    const int tid = threadIdx.x;
    const int bn = blockIdx.x * 128;
    const int ks = blockIdx.y;
    const int k_begin = ks * (H_SZ / KSPLIT);
    const int tx = tid & 31;        // N dir: 32 * 4
    const int ty = tid >> 5;        // M dir: 8 * 8

    float acc[8][4];
#pragma unroll
    for (int i = 0; i < 8; i++)
#pragma unroll
        for (int j = 0; j < 4; j++) acc[i][j] = 0.f;

    for (int k0 = k_begin; k0 < k_begin + H_SZ / KSPLIT; k0 += 16) {
        {   // A tile 64x16 = 256 float4, 1 per thread
            int row = tid >> 2;
            int kq = (tid & 3) * 4;
            float4 v = *(const float4*)&g_h[row * H_SZ + k0 + kq];
            As[kq + 0][row] = v.x; As[kq + 1][row] = v.y;
            As[kq + 2][row] = v.z; As[kq + 3][row] = v.w;
        }
#pragma unroll
        for (int t = 0; t < 2; t++) {   // B tile 16x128 = 512 float4
            int idx = tid + t * 256;
            int row = idx >> 5;
            int c4 = (idx & 31) * 4;
            *(float4*)&Bs[row][c4] =
                *(const float4*)&Wh[(size_t)(k0 + row) * G_SZ + bn + c4];
        }
        __syncthreads();
#pragma unroll
        for (int k = 0; k < 16; k++) {
            float a[8], b[4];
            *(float4*)&a[0] = *(const float4*)&As[k][ty * 8];
            *(float4*)&a[4] = *(const float4*)&As[k][ty * 8 + 4];
            *(float4*)&b[0] = *(const float4*)&Bs[k][tx * 4];
#pragma unroll
            for (int i = 0; i < 8; i++)
#pragma unroll
                for (int j = 0; j < 4; j++) acc[i][j] = fmaf(a[i], b[j], acc[i][j]);
        }
        __syncthreads();
    }

    float* zp = g_zpart[ks];
#pragma unroll
    for (int i = 0; i < 8; i++) {
        int row = ty * 8 + i;
        float4 o = make_float4(acc[i][0], acc[i][1], acc[i][2], acc[i][3]);
        *(float4*)&zp[(size_t)row * G_SZ + bn + tx * 4] = o;
    }
}

// ---------------- gate pointwise: c,h update + sequence scatter ------------
__device__ __forceinline__ float sigmoidf_(float x) { return 1.f / (1.f + expf(-x)); }

__global__ __launch_bounds__(256) void lstm_gates(
    const float* __restrict__ zx_t, float* __restrict__ hseq, int t)
{
    const int idx = blockIdx.x * 256 + threadIdx.x;   // 0..65535
    const int b = idx >> 10;
    const int u = idx & 1023;
    const size_t base = (size_t)b * G_SZ;

    float zi = zx_t[base + u];
    float zf = zx_t[base + H_SZ + u];
    float zg = zx_t[base + 2 * H_SZ + u];
    float zo = zx_t[base + 3 * H_SZ + u];
#pragma unroll
    for (int s = 0; s < KSPLIT; s++) {
        zi += g_zpart[s][base + u];
        zf += g_zpart[s][base + H_SZ + u];
        zg += g_zpart[s][base + 2 * H_SZ + u];
        zo += g_zpart[s][base + 3 * H_SZ + u];
    }
    const float ig = sigmoidf_(zi);
    const float fg = sigmoidf_(zf);
    const float gg = tanhf(zg);
    const float og = sigmoidf_(zo);
    const float c_new = fg * g_c[idx] + ig * gg;
    const float h_new = og * tanhf(c_new);
    g_c[idx] = c_new;
    g_h[idx] = h_new;
    hseq[((size_t)b * T_SZ + t) * H_SZ + u] = h_new;
}

// ---------------- state init / export --------------------------------------
__global__ __launch_bounds__(256) void copy_state(
    const float* __restrict__ c0, const float* __restrict__ h0)
{
    int i = blockIdx.x * 256 + threadIdx.x;
    g_c[i] = c0[i];
    g_h[i] = h0[i];
}

__global__ __launch_bounds__(256) void copy_out(
    float* __restrict__ dst_c, float* __restrict__ dst_h)
{
    int i = blockIdx.x * 256 + threadIdx.x;
    dst_c[i] = g_c[i];
    dst_h[i] = g_h[i];
}

// ---------------- launch ----------------------------------------------------
extern "C" void kernel_launch(void* const* d_in, const int* in_sizes, int n_in,
                              void* d_out, int out_size)
{
    const float* x        = (const float*)d_in[0];
    const float* c0       = (const float*)d_in[1];
    const float* h0       = (const float*)d_in[2];
    const float* W_pre    = (const float*)d_in[3];
    const float* b_pre    = (const float*)d_in[4];
    const float* ln_scale = (const float*)d_in[5];
    const float* ln_bias  = (const float*)d_in[6];
    const float* Wi0      = (const float*)d_in[7];
    const float* Wh0      = (const float*)d_in[8];
    const float* b0       = (const float*)d_in[9];
    const float* Wi1      = (const float*)d_in[10];
    const float* Wh1      = (const float*)d_in[11];
    const float* b1       = (const float*)d_in[12];
    const float* W_post   = (const float*)d_in[13];
    const float* b_post   = (const float*)d_in[14];
    const float* W_out    = (const float*)d_in[15];
    const float* b_out    = (const float*)d_in[16];
    float* out = (float*)d_out;

    float* g_pre_p;   cudaGetSymbolAddress((void**)&g_pre_p, g_pre);
    float* g_zx_p;    cudaGetSymbolAddress((void**)&g_zx_p, g_zx);
    float* g_hseq0_p; cudaGetSymbolAddress((void**)&g_hseq0_p, g_hseq0);
    float* g_hseq1_p; cudaGetSymbolAddress((void**)&g_hseq1_p, g_hseq1);
    float* g_hp_p;    cudaGetSymbolAddress((void**)&g_hp_p, g_hp);

    // 1) pre dense: [8192,512]@[512,1024]
    gemm_main<0, 0><<<dim3(P_SZ / 64, R_SZ / 128), 256>>>(
        x, W_pre, b_pre, g_pre_p, R_SZ, P_SZ, F_SZ);
    // 2) LayerNorm + ReLU, in place
    ln_relu_kernel<<<R_SZ, 256>>>(g_pre_p, ln_scale, ln_bias);
    // 3) layer-0 input gates, time-major: [8192,1024]@[1024,4096]
    gemm_main<0, 1><<<dim3(G_SZ / 64, R_SZ / 128), 256>>>(
        g_pre_p, Wi0, b0, g_zx_p, R_SZ, G_SZ, P_SZ);

    // 4) layer-0 recurrence
    copy_state<<<256, 256>>>(c0, h0);
    for (int t = 0; t < T_SZ; t++) {
        lstm_gemm<<<dim3(G_SZ / 128, KSPLIT), 256>>>(Wh0);
        lstm_gates<<<256, 256>>>(g_zx_p + (size_t)t * B_SZ * G_SZ, g_hseq0_p, t);
    }
    copy_out<<<256, 256>>>(out, out + 2 * B_SZ * H_SZ);   // c1, h1

    // 5) layer-1 input gates (reuse g_zx)
    gemm_main<0, 1><<<dim3(G_SZ / 64, R_SZ / 128), 256>>>(
        g_hseq0_p, Wi1, b1, g_zx_p, R_SZ, G_SZ, H_SZ);

    // 6) layer-1 recurrence
    copy_state<<<256, 256>>>(c0 + B_SZ * H_SZ, h0 + B_SZ * H_SZ);
    for (int t = 0; t < T_SZ; t++) {
        lstm_gemm<<<dim3(G_SZ / 128, KSPLIT), 256>>>(Wh1);
        lstm_gates<<<256, 256>>>(g_zx_p + (size_t)t * B_SZ * G_SZ, g_hseq1_p, t);
    }
    copy_out<<<256, 256>>>(out + B_SZ * H_SZ, out + 3 * B_SZ * H_SZ);  // c2, h2

    // 7) post dense + relu: [8192,1024]@[1024,1024]
    gemm_main<1, 0><<<dim3(P_SZ / 64, R_SZ / 128), 256>>>(
        g_hseq1_p, W_post, b_post, g_hp_p, R_SZ, P_SZ, H_SZ);
    // 8) logits: [8192,1024]@[1024,32] -> out[262144:]
    gemm_main<0, 0><<<dim3(1, R_SZ / 128), 256>>>(
        g_hp_p, W_out, b_out, out + 4 * B_SZ * H_SZ, R_SZ, A_SZ, P_SZ);
}

// round 5
// speedup vs baseline: 1.8004x; 1.7226x over previous
#include <cuda_runtime.h>
#include <cuda_bf16.h>
#include <math.h>
#include <stdint.h>

#define B_SZ 64
#define T_SZ 128
#define F_SZ 512
#define H_SZ 1024
#define P_SZ 1024
#define A_SZ 32
#define R_SZ 8192
#define G_SZ 4096
#define KSPLIT 3
#define S_ST 3          /* cp.async pipeline stages */

typedef __nv_bfloat16 bf16;

// ---------------- scratch (static device globals) ---------------------------
__device__ float g_pre[(size_t)R_SZ * P_SZ];
__device__ float g_zx[(size_t)R_SZ * G_SZ];              // time-major [T][B][4H]
__device__ float g_zpart[KSPLIT][(size_t)B_SZ * G_SZ];   // split-K partials
__device__ float g_c[B_SZ * H_SZ];
__device__ float g_h[B_SZ * H_SZ];
__device__ float g_zbias[G_SZ];                          // stays zero

__device__ __align__(256) bf16 g_Ax  [(size_t)R_SZ * 3 * F_SZ];
__device__ __align__(256) bf16 g_Aln [(size_t)R_SZ * 3 * P_SZ];
__device__ __align__(256) bf16 g_Aseq0[(size_t)R_SZ * 3 * H_SZ];
__device__ __align__(256) bf16 g_Aseq1[(size_t)R_SZ * 3 * H_SZ];
__device__ __align__(256) bf16 g_Ahp [(size_t)R_SZ * 3 * P_SZ];
__device__ __align__(256) bf16 g_Ah  [B_SZ * 3 * H_SZ];

__device__ __align__(256) bf16 g_Bpre [(size_t)P_SZ * 3 * F_SZ];
__device__ __align__(256) bf16 g_Bwi0 [(size_t)G_SZ * 3 * P_SZ];
__device__ __align__(256) bf16 g_Bwh0 [(size_t)G_SZ * 3 * H_SZ];
__device__ __align__(256) bf16 g_Bwi1 [(size_t)G_SZ * 3 * H_SZ];
__device__ __align__(256) bf16 g_Bwh1 [(size_t)G_SZ * 3 * H_SZ];
__device__ __align__(256) bf16 g_Bpost[(size_t)P_SZ * 3 * H_SZ];
__device__ __align__(256) bf16 g_Bout [(size_t)A_SZ * 3 * P_SZ];

// ---------------- helpers ---------------------------------------------------
__device__ __forceinline__ uint32_t smem_u32(const void* p) {
    uint32_t a;
    asm("{ .reg .u64 t; cvta.to.shared.u64 t, %1; cvt.u32.u64 %0, t; }" : "=r"(a) : "l"(p));
    return a;
}
#define SMEM_SWZ(o) ((o) ^ (((o) >> 3) & 0x70))
#define CP_ASYNC16(dst, src) \
    asm volatile("cp.async.cg.shared.global [%0], [%1], 16;" :: "r"(dst), "l"(src))
#define CP_COMMIT() asm volatile("cp.async.commit_group;" ::: "memory")
#define CP_WAIT2()  asm volatile("cp.async.wait_group 2;" ::: "memory")

__device__ __forceinline__ void ldmx4(uint32_t* r, uint32_t addr) {
    asm volatile("ldmatrix.sync.aligned.m8n8.x4.shared.b16 {%0,%1,%2,%3}, [%4];"
                 : "=r"(r[0]), "=r"(r[1]), "=r"(r[2]), "=r"(r[3]) : "r"(addr));
}
__device__ __forceinline__ void mma16816(float* c, const uint32_t* a, const uint32_t* b) {
    asm volatile("mma.sync.aligned.m16n8k16.row.col.f32.bf16.bf16.f32 "
                 "{%0,%1,%2,%3}, {%4,%5,%6,%7}, {%8,%9}, {%0,%1,%2,%3};"
                 : "+f"(c[0]), "+f"(c[1]), "+f"(c[2]), "+f"(c[3])
                 : "r"(a[0]), "r"(a[1]), "r"(a[2]), "r"(a[3]), "r"(b[0]), "r"(b[1]));
}
__device__ __forceinline__ void split2(float v, bf16& hi, bf16& lo) {
    hi = __float2bfloat16_rn(v);
    lo = __float2bfloat16_rn(v - __bfloat162float(hi));
}

// ---------------- HMMA GEMM: C[M,Ntot] = A'[M,K3] @ B'[Ntot,K3]^T -----------
// K chunks of 64 bf16 (128B rows, SW128 swizzle). blockIdx.z = split-K slice.
// OUTMODE 0: fp32 row-major (+bias). 1: fp32 time-major [T][B][Ntot] (+bias).
//         2: bf16-split [M, 3*Ntot] (+bias, relu).
template <int BM, int BN, int OUTMODE>
__global__ __launch_bounds__(256, 1) void gemm_mma(
    const bf16* __restrict__ Ap, const bf16* __restrict__ Bp,
    const float* __restrict__ bias, float* __restrict__ Cf,
    bf16* __restrict__ Cb, int Ntot, int K3, int KS)
{
    constexpr int WM = (BM == 64) ? 1 : ((BN == 32) ? 4 : 2);
    constexpr int WN = 8 / WM;
    constexpr int TM = BM / WM;
    constexpr int TN = BN / WN;
    constexpr int MT = TM / 16;
    constexpr int NT = TN / 8;
    constexpr int ABYTES = BM * 128;
    constexpr int BBYTES = BN * 128;

    extern __shared__ __align__(128) char smem[];
    const uint32_t sA = smem_u32(smem);
    const uint32_t sB = sA + S_ST * ABYTES;

    const int tid = threadIdx.x;
    const int lane = tid & 31, wid = tid >> 5;
    const int wm = wid % WM, wn = wid / WM;
    const int bm = blockIdx.y * BM;
    const int bn = blockIdx.x * BN;
    const int NC = K3 / (64 * KS);
    const int cbeg = blockIdx.z * NC;
    const int Mtot = gridDim.y * BM;

    float* Cfo = Cf + (size_t)blockIdx.z * Mtot * Ntot;   // split-K partial slab

    const char* Ag = (const char*)(Ap + (size_t)bm * K3);
    const char* Bg = (const char*)(Bp + (size_t)bn * K3);
    const size_t rowB = (size_t)K3 * 2;

    float acc[MT][NT][4];
#pragma unroll
    for (int i = 0; i < MT; i++)
#pragma unroll
        for (int j = 0; j < NT; j++)
#pragma unroll
            for (int q = 0; q < 4; q++) acc[i][j][q] = 0.f;

    auto load_chunk = [&](int c, int stage) {
        const size_t coff = (size_t)(cbeg + c) * 128;
        const uint32_t aT = sA + stage * ABYTES;
        const uint32_t bT = sB + stage * BBYTES;
#pragma unroll
        for (int i = 0; i < BM / 32; i++) {
            int seg = tid + i * 256, row = seg >> 3, so = (seg & 7) * 16;
            CP_ASYNC16(aT + SMEM_SWZ(row * 128 + so), Ag + (size_t)row * rowB + coff + so);
        }
#pragma unroll
        for (int i = 0; i < BN / 32; i++) {
            int seg = tid + i * 256, row = seg >> 3, so = (seg & 7) * 16;
            CP_ASYNC16(bT + SMEM_SWZ(row * 128 + so), Bg + (size_t)row * rowB + coff + so);
        }
    };

    load_chunk(0, 0); CP_COMMIT();
    load_chunk(1, 1); CP_COMMIT();

    // per-lane ldmatrix address components
    const int a_row = wm * TM + (lane & 15);        // + i*16
    const int a_k16 = (lane >> 4) * 16;             // 16B offset within kstep
    const int b_row = wn * TN + (lane & 7) + ((lane >> 4) << 3);  // + jp*16
    const int b_k16 = ((lane >> 3) & 1) * 16;

    for (int c = 0; c < NC; c++) {
        int n = c + 2;
        if (n < NC) load_chunk(n, n % S_ST);
        CP_COMMIT();
        CP_WAIT2();
        __syncthreads();

        const uint32_t aT = sA + (c % S_ST) * ABYTES;
        const uint32_t bT = sB + (c % S_ST) * BBYTES;
#pragma unroll
        for (int ks = 0; ks < 4; ks++) {
            uint32_t af[MT][4], bfr[NT][2];
#pragma unroll
            for (int i = 0; i < MT; i++)
                ldmx4(af[i], aT + SMEM_SWZ((a_row + i * 16) * 128 + ks * 32 + a_k16));
#pragma unroll
            for (int jp = 0; jp < NT / 2; jp++) {
                uint32_t t4[4];
                ldmx4(t4, bT + SMEM_SWZ((b_row + jp * 16) * 128 + ks * 32 + b_k16));
                bfr[2 * jp][0] = t4[0]; bfr[2 * jp][1] = t4[1];
                bfr[2 * jp + 1][0] = t4[2]; bfr[2 * jp + 1][1] = t4[3];
            }
#pragma unroll
            for (int i = 0; i < MT; i++)
#pragma unroll
                for (int j = 0; j < NT; j++)
                    mma16816(acc[i][j], af[i], bfr[j]);
        }
        __syncthreads();
    }

    // ---------------- epilogue ----------------
#pragma unroll
    for (int i = 0; i < MT; i++) {
        const int r0 = bm + wm * TM + i * 16 + (lane >> 2);
        const int r1 = r0 + 8;
#pragma unroll
        for (int j = 0; j < NT; j++) {
            const int col = bn + wn * TN + j * 8 + (lane & 3) * 2;
            const float2 bv = *(const float2*)&bias[col];
            float v00 = acc[i][j][0] + bv.x, v01 = acc[i][j][1] + bv.y;
            float v10 = acc[i][j][2] + bv.x, v11 = acc[i][j][3] + bv.y;
            if (OUTMODE == 0) {
                *(float2*)&Cfo[(size_t)r0 * Ntot + col] = make_float2(v00, v01);
                *(float2*)&Cfo[(size_t)r1 * Ntot + col] = make_float2(v10, v11);
            } else if (OUTMODE == 1) {
                int b0i = r0 >> 7, t0 = r0 & 127, b1i = r1 >> 7, t1 = r1 & 127;
                *(float2*)&Cfo[((size_t)t0 * B_SZ + b0i) * Ntot + col] = make_float2(v00, v01);
                *(float2*)&Cfo[((size_t)t1 * B_SZ + b1i) * Ntot + col] = make_float2(v10, v11);
            } else {
                v00 = fmaxf(v00, 0.f); v01 = fmaxf(v01, 0.f);
                v10 = fmaxf(v10, 0.f); v11 = fmaxf(v11, 0.f);
                bf16 h0, l0, h1, l1;
                bf16* row0 = Cb + (size_t)r0 * 3 * Ntot;
                bf16* row1 = Cb + (size_t)r1 * 3 * Ntot;
                split2(v00, h0, l0); split2(v01, h1, l1);
                *(__nv_bfloat162*)&row0[col] = __nv_bfloat162(h0, h1);
                *(__nv_bfloat162*)&row0[Ntot + col] = __nv_bfloat162(h0, h1);
                *(__nv_bfloat162*)&row0[2 * Ntot + col] = __nv_bfloat162(l0, l1);
                split2(v10, h0, l0); split2(v11, h1, l1);
                *(__nv_bfloat162*)&row1[col] = __nv_bfloat162(h0, h1);
                *(__nv_bfloat162*)&row1[Ntot + col] = __nv_bfloat162(h0, h1);
                *(__nv_bfloat162*)&row1[2 * Ntot + col] = __nv_bfloat162(l0, l1);
            }
        }
    }
}

// ---------------- weight convert: W[K,N] -> B'[N,3K] = [hi|lo|hi] -----------
__global__ __launch_bounds__(256) void conv_w(const float* __restrict__ W,
                                              bf16* __restrict__ Bp, int K, int N)
{
    __shared__ float tile[32][33];
    const int n0 = blockIdx.x * 32, k0 = blockIdx.y * 32;
    const int tx = threadIdx.x & 31, ty = threadIdx.x >> 5;
    for (int i = ty; i < 32; i += 8)
        tile[i][tx] = W[(size_t)(k0 + i) * N + n0 + tx];
    __syncthreads();
    for (int i = ty; i < 32; i += 8) {
        int n = n0 + i, k = k0 + tx;
        bf16 hi, lo; split2(tile[tx][i], hi, lo);
        bf16* row = Bp + (size_t)n * 3 * K;
        row[k] = hi; row[K + k] = lo; row[2 * K + k] = hi;
    }
}

// ---------------- activation convert: X[M,K] -> A'[M,3K] = [hi|hi|lo] -------
__global__ __launch_bounds__(256) void conv_x(const float* __restrict__ X,
                                              bf16* __restrict__ Ap, int K, int total)
{
    int i = blockIdx.x * 256 + threadIdx.x;
    if (i >= total) return;
    int r = i / K, k = i - r * K;
    bf16 hi, lo; split2(X[i], hi, lo);
    bf16* row = Ap + (size_t)r * 3 * K;
    row[k] = hi; row[K + k] = hi; row[2 * K + k] = lo;
}

// ---------------- LayerNorm + ReLU -> split bf16 ----------------------------
__global__ __launch_bounds__(256) void ln_relu(const float* __restrict__ buf,
    const float* __restrict__ gamma, const float* __restrict__ beta,
    bf16* __restrict__ Ap)
{
    __shared__ float rs[8], rs2[8];
    const int row = blockIdx.x;
    const float* p = buf + (size_t)row * P_SZ;
    const int tid = threadIdx.x;
    float4 v = *(const float4*)&p[tid * 4];
    float s = v.x + v.y + v.z + v.w;
    float s2 = v.x * v.x + v.y * v.y + v.z * v.z + v.w * v.w;
#pragma unroll
    for (int off = 16; off > 0; off >>= 1) {
        s += __shfl_xor_sync(0xFFFFFFFFu, s, off);
        s2 += __shfl_xor_sync(0xFFFFFFFFu, s2, off);
    }
    if ((tid & 31) == 0) { rs[tid >> 5] = s; rs2[tid >> 5] = s2; }
    __syncthreads();
    float tot = 0.f, tot2 = 0.f;
#pragma unroll
    for (int i = 0; i < 8; i++) { tot += rs[i]; tot2 += rs2[i]; }
    const float mu = tot * (1.f / 1024.f);
    const float r = rsqrtf(tot2 * (1.f / 1024.f) - mu * mu + 1e-6f);
    float4 g = *(const float4*)&gamma[tid * 4];
    float4 b = *(const float4*)&beta[tid * 4];
    float o[4] = { fmaxf((v.x - mu) * r * g.x + b.x, 0.f),
                   fmaxf((v.y - mu) * r * g.y + b.y, 0.f),
                   fmaxf((v.z - mu) * r * g.z + b.z, 0.f),
                   fmaxf((v.w - mu) * r * g.w + b.w, 0.f) };
    bf16* rp = Ap + (size_t)row * 3 * P_SZ;
#pragma unroll
    for (int q = 0; q < 4; q++) {
        int k = tid * 4 + q;
        bf16 hi, lo; split2(o[q], hi, lo);
        rp[k] = hi; rp[P_SZ + k] = hi; rp[2 * P_SZ + k] = lo;
    }
}

// ---------------- LSTM gates ------------------------------------------------
__device__ __forceinline__ float sigmoidf_(float x) { return 1.f / (1.f + expf(-x)); }

__global__ __launch_bounds__(256) void lstm_gates(
    const float* __restrict__ zx_t, bf16* __restrict__ Aseq, int t)
{
    const int idx = blockIdx.x * 256 + threadIdx.x;
    const int b = idx >> 10, u = idx & 1023;
    const size_t base = (size_t)b * G_SZ;
    float zi = zx_t[base + u];
    float zf = zx_t[base + H_SZ + u];
    float zg = zx_t[base + 2 * H_SZ + u];
    float zo = zx_t[base + 3 * H_SZ + u];
#pragma unroll
    for (int s = 0; s < KSPLIT; s++) {
        zi += g_zpart[s][base + u];
        zf += g_zpart[s][base + H_SZ + u];
        zg += g_zpart[s][base + 2 * H_SZ + u];
        zo += g_zpart[s][base + 3 * H_SZ + u];
    }
    const float c_new = sigmoidf_(zf) * g_c[idx] + sigmoidf_(zi) * tanhf(zg);
    const float h_new = sigmoidf_(zo) * tanhf(c_new);
    g_c[idx] = c_new;
    g_h[idx] = h_new;
    bf16 hi, lo; split2(h_new, hi, lo);
    bf16* ra = g_Ah + (size_t)b * 3 * H_SZ;
    ra[u] = hi; ra[H_SZ + u] = hi; ra[2 * H_SZ + u] = lo;
    bf16* rq = Aseq + ((size_t)b * T_SZ + t) * 3 * H_SZ;
    rq[u] = hi; rq[H_SZ + u] = hi; rq[2 * H_SZ + u] = lo;
}

// ---------------- state init / export ---------------------------------------
__global__ __launch_bounds__(256) void init_state(
    const float* __restrict__ c0, const float* __restrict__ h0)
{
    int i = blockIdx.x * 256 + threadIdx.x;       // 0 .. 64*1024-1
    int b = i >> 10, u = i & 1023;
    g_c[i] = c0[i];
    g_h[i] = h0[i];
    bf16 hi, lo; split2(h0[i], hi, lo);
    bf16* ra = g_Ah + (size_t)b * 3 * H_SZ;
    ra[u] = hi; ra[H_SZ + u] = hi; ra[2 * H_SZ + u] = lo;
}
__global__ __launch_bounds__(256) void copy_out(float* dst_c, float* dst_h)
{
    int i = blockIdx.x * 256 + threadIdx.x;
    dst_c[i] = g_c[i];
    dst_h[i] = g_h[i];
}

// ---------------- launch -----------------------------------------------------
extern "C" void kernel_launch(void* const* d_in, const int* in_sizes, int n_in,
                              void* d_out, int out_size)
{
    const float* x        = (const float*)d_in[0];
    const float* c0       = (const float*)d_in[1];
    const float* h0       = (const float*)d_in[2];
    const float* W_pre    = (const float*)d_in[3];
    const float* b_pre    = (const float*)d_in[4];
    const float* ln_scale = (const float*)d_in[5];
    const float* ln_bias  = (const float*)d_in[6];
    const float* Wi0      = (const float*)d_in[7];
    const float* Wh0      = (const float*)d_in[8];
    const float* b0       = (const float*)d_in[9];
    const float* Wi1      = (const float*)d_in[10];
    const float* Wh1      = (const float*)d_in[11];
    const float* b1       = (const float*)d_in[12];
    const float* W_post   = (const float*)d_in[13];
    const float* b_post   = (const float*)d_in[14];
    const float* W_out    = (const float*)d_in[15];
    const float* b_out    = (const float*)d_in[16];
    float* out = (float*)d_out;

    float *pre_p, *zx_p, *zpart_p, *zb_p;
    bf16 *Ax, *Aln, *As0, *As1, *Ahp, *Ah;
    bf16 *Bpre, *Bwi0, *Bwh0, *Bwi1, *Bwh1, *Bpost, *Bout;
    cudaGetSymbolAddress((void**)&pre_p, g_pre);
    cudaGetSymbolAddress((void**)&zx_p, g_zx);
    cudaGetSymbolAddress((void**)&zpart_p, g_zpart);
    cudaGetSymbolAddress((void**)&zb_p, g_zbias);
    cudaGetSymbolAddress((void**)&Ax, g_Ax);
    cudaGetSymbolAddress((void**)&Aln, g_Aln);
    cudaGetSymbolAddress((void**)&As0, g_Aseq0);
    cudaGetSymbolAddress((void**)&As1, g_Aseq1);
    cudaGetSymbolAddress((void**)&Ahp, g_Ahp);
    cudaGetSymbolAddress((void**)&Ah, g_Ah);
    cudaGetSymbolAddress((void**)&Bpre, g_Bpre);
    cudaGetSymbolAddress((void**)&Bwi0, g_Bwi0);
    cudaGetSymbolAddress((void**)&Bwh0, g_Bwh0);
    cudaGetSymbolAddress((void**)&Bwi1, g_Bwi1);
    cudaGetSymbolAddress((void**)&Bwh1, g_Bwh1);
    cudaGetSymbolAddress((void**)&Bpost, g_Bpost);
    cudaGetSymbolAddress((void**)&Bout, g_Bout);

    const int SMEM_128_128 = S_ST * (128 + 128) * 128;   // 98304
    const int SMEM_64_128  = S_ST * (64 + 128) * 128;    // 73728
    const int SMEM_128_32  = S_ST * (128 + 32) * 128;    // 61440
    cudaFuncSetAttribute(gemm_mma<128, 128, 0>, cudaFuncAttributeMaxDynamicSharedMemorySize, SMEM_128_128);
    cudaFuncSetAttribute(gemm_mma<128, 128, 1>, cudaFuncAttributeMaxDynamicSharedMemorySize, SMEM_128_128);
    cudaFuncSetAttribute(gemm_mma<128, 128, 2>, cudaFuncAttributeMaxDynamicSharedMemorySize, SMEM_128_128);
    cudaFuncSetAttribute(gemm_mma<64, 128, 0>,  cudaFuncAttributeMaxDynamicSharedMemorySize, SMEM_64_128);
    cudaFuncSetAttribute(gemm_mma<128, 32, 0>,  cudaFuncAttributeMaxDynamicSharedMemorySize, SMEM_128_32);

    // weight + input conversion
    conv_w<<<dim3(P_SZ / 32, F_SZ / 32), 256>>>(W_pre, Bpre, F_SZ, P_SZ);
    conv_w<<<dim3(G_SZ / 32, P_SZ / 32), 256>>>(Wi0, Bwi0, P_SZ, G_SZ);
    conv_w<<<dim3(G_SZ / 32, H_SZ / 32), 256>>>(Wh0, Bwh0, H_SZ, G_SZ);
    conv_w<<<dim3(G_SZ / 32, H_SZ / 32), 256>>>(Wi1, Bwi1, H_SZ, G_SZ);
    conv_w<<<dim3(G_SZ / 32, H_SZ / 32), 256>>>(Wh1, Bwh1, H_SZ, G_SZ);
    conv_w<<<dim3(P_SZ / 32, H_SZ / 32), 256>>>(W_post, Bpost, H_SZ, P_SZ);
    conv_w<<<dim3(A_SZ / 32, P_SZ / 32), 256>>>(W_out, Bout, P_SZ, A_SZ);
    conv_x<<<(R_SZ * F_SZ + 255) / 256, 256>>>(x, Ax, F_SZ, R_SZ * F_SZ);

    // pre dense -> fp32, then LN+relu -> split bf16
    gemm_mma<128, 128, 0><<<dim3(P_SZ / 128, R_SZ / 128, 1), 256, SMEM_128_128>>>(
        Ax, Bpre, b_pre, pre_p, nullptr, P_SZ, 3 * F_SZ, 1);
    ln_relu<<<R_SZ, 256>>>(pre_p, ln_scale, ln_bias, Aln);

    // layer-0 input gates (time-major)
    gemm_mma<128, 128, 1><<<dim3(G_SZ / 128, R_SZ / 128, 1), 256, SMEM_128_128>>>(
        Aln, Bwi0, b0, zx_p, nullptr, G_SZ, 3 * P_SZ, 1);

    init_state<<<256, 256>>>(c0, h0);
    for (int t = 0; t < T_SZ; t++) {
        gemm_mma<64, 128, 0><<<dim3(G_SZ / 128, 1, KSPLIT), 256, SMEM_64_128>>>(
            Ah, Bwh0, zb_p, zpart_p, nullptr, G_SZ, 3 * H_SZ, KSPLIT);
        lstm_gates<<<256, 256>>>(zx_p + (size_t)t * B_SZ * G_SZ, As0, t);
    }
    copy_out<<<256, 256>>>(out, out + 2 * B_SZ * H_SZ);               // c1, h1

    // layer-1 input gates
    gemm_mma<128, 128, 1><<<dim3(G_SZ / 128, R_SZ / 128, 1), 256, SMEM_128_128>>>(
        As0, Bwi1, b1, zx_p, nullptr, G_SZ, 3 * H_SZ, 1);

    init_state<<<256, 256>>>(c0 + B_SZ * H_SZ, h0 + B_SZ * H_SZ);
    for (int t = 0; t < T_SZ; t++) {
        gemm_mma<64, 128, 0><<<dim3(G_SZ / 128, 1, KSPLIT), 256, SMEM_64_128>>>(
            Ah, Bwh1, zb_p, zpart_p, nullptr, G_SZ, 3 * H_SZ, KSPLIT);
        lstm_gates<<<256, 256>>>(zx_p + (size_t)t * B_SZ * G_SZ, As1, t);
    }
    copy_out<<<256, 256>>>(out + B_SZ * H_SZ, out + 3 * B_SZ * H_SZ); // c2, h2

    // post dense + relu -> split bf16, then logits
    gemm_mma<128, 128, 2><<<dim3(P_SZ / 128, R_SZ / 128, 1), 256, SMEM_128_128>>>(
        As1, Bpost, b_post, nullptr, Ahp, P_SZ, 3 * H_SZ, 1);
    gemm_mma<128, 32, 0><<<dim3(1, R_SZ / 128, 1), 256, SMEM_128_32>>>(
        Ahp, Bout, b_out, out + 4 * B_SZ * H_SZ, nullptr, A_SZ, 3 * P_SZ, 1);
}